// round 6
// baseline (speedup 1.0000x reference)
#include <cuda_runtime.h>
#include <cuda_bf16.h>

// Problem constants (from reference_code)
#define Bn   2
#define NH   8
#define KW   5
#define KK   25       // 5x5 neighbor offsets
#define HD   16       // head_dim = 128/8
#define HC   48       // coarse H
#define WC   48       // coarse W
#define OH   96       // query_height
#define OW   96       // query_width
// scale_factor = 2, dilation = 1, radius = 2

// Output layout: concat(k_nb, v_nb, mask); every plane is 96*96 = 9216 floats.
//   k_nb planes:  [0, 6400)        plane p = ((b*NH + h)*KK + kk)*HD + d
//   v_nb planes:  [6400, 12800)
//   mask planes:  [12800, 13200)   plane p = (b*NH + h)*KK + kk
constexpr int PLANE_KV        = Bn * NH * KK * HD;              // 6400
constexpr int PLANE_MASK_BASE = 2 * PLANE_KV;                   // 12800
constexpr int PLANES          = PLANE_MASK_BASE + Bn * NH * KK; // 13200

constexpr int Q4_PER_ROW = OW / 4;     // 24 float4 per fine row
constexpr int RHALF      = HC / 2;     // 24: thread covers cr and cr+24
constexpr int TPB        = Q4_PER_ROW * RHALF;  // 576
constexpr int TILE_F     = HC * WC;    // 2304 floats = 576 float4

__device__ __forceinline__ void stcs4(float4* p, float4 v) {
    asm volatile("st.global.cs.v4.f32 [%0], {%1, %2, %3, %4};"
                 :: "l"(p), "f"(v.x), "f"(v.y), "f"(v.z), "f"(v.w) : "memory");
}

__global__ void __launch_bounds__(TPB)
xsn_extract_kernel(const float* __restrict__ kin,
                   const float* __restrict__ vin,
                   float* __restrict__ out)
{
    __shared__ float tile[TILE_F];   // 9216 B: whole 48x48 coarse channel

    // ---- block-uniform plane decode (one block == one output plane) ----
    const int plane = blockIdx.x;

    const float* src = kin;
    int p = plane;
    bool is_mask = false;
    if (plane >= PLANE_MASK_BASE) {
        is_mask = true;
        p = plane - PLANE_MASK_BASE;
    } else if (plane >= PLANE_KV) {
        src = vin;
        p = plane - PLANE_KV;
    }

    int kk, base = 0;
    if (is_mask) {
        kk = p % KK;                           // p = bh*25 + kk
    } else {
        int d    = p & (HD - 1);               // p = (bh*25 + kk)*16 + d
        int rest = p >> 4;
        kk       = rest % KK;
        int bh   = rest / KK;                  // b*NH + h
        base     = (bh * HD + d) * TILE_F;     // channel = bh*16 + d
    }
    const int dy = kk / KW - 2;
    const int dx = kk - (kk / KW) * KW - 2;

    const int qx = threadIdx.x;   // 0..23 (float4 column in fine row)
    const int cr = threadIdx.y;   // 0..23 (base coarse row)

    // ---- stage: one coalesced float4 load per thread covers the whole tile ----
    if (!is_mask) {
        const int t = cr * Q4_PER_ROW + qx;    // 0..575
        reinterpret_cast<float4*>(tile)[t] =
            __ldg(reinterpret_cast<const float4*>(src + base) + t);
    }
    __syncthreads();

    const int xc0 = (qx << 1) + dx;
    const int xc1 = xc0 + 1;
    const bool bx0 = (unsigned)xc0 < (unsigned)WC;
    const bool bx1 = (unsigned)xc1 < (unsigned)WC;

    const int ycA = cr + dy;
    const int ycB = cr + RHALF + dy;
    const bool vyA = (unsigned)ycA < (unsigned)HC;
    const bool vyB = (unsigned)ycB < (unsigned)HC;

    float a0, a1, b0, b1;
    if (is_mask) {
        a0 = (vyA && bx0) ? 1.0f : 0.0f;
        a1 = (vyA && bx1) ? 1.0f : 0.0f;
        b0 = (vyB && bx0) ? 1.0f : 0.0f;
        b1 = (vyB && bx1) ? 1.0f : 0.0f;
    } else {
        a0 = (vyA && bx0) ? tile[ycA * WC + xc0] : 0.0f;
        a1 = (vyA && bx1) ? tile[ycA * WC + xc1] : 0.0f;
        b0 = (vyB && bx0) ? tile[ycB * WC + xc0] : 0.0f;
        b1 = (vyB && bx1) ? tile[ycB * WC + xc1] : 0.0f;
    }

    const float4 oA = make_float4(a0, a0, a1, a1);
    const float4 oB = make_float4(b0, b0, b1, b1);

    // fine rows 2*cr, 2*cr+1 (copy A); 2*(cr+24), 2*(cr+24)+1 (copy B)
    float4* dst = reinterpret_cast<float4*>(out)
                + plane * (OH * Q4_PER_ROW)            // plane * 2304
                + cr * (2 * Q4_PER_ROW)
                + qx;
    stcs4(dst,                                oA);
    stcs4(dst + Q4_PER_ROW,                   oA);
    stcs4(dst + 2 * RHALF * Q4_PER_ROW,       oB);     // +1152
    stcs4(dst + (2 * RHALF + 1) * Q4_PER_ROW, oB);     // +1176
}

extern "C" void kernel_launch(void* const* d_in, const int* in_sizes, int n_in,
                              void* d_out, int out_size)
{
    const float* k = (const float*)d_in[0];
    const float* v = (const float*)d_in[1];
    float* out = (float*)d_out;

    dim3 block(Q4_PER_ROW, RHALF, 1);   // (24, 24) = 576 threads
    xsn_extract_kernel<<<PLANES, block>>>(k, v, out);
}

// round 7
// speedup vs baseline: 1.6807x; 1.6807x over previous
#include <cuda_runtime.h>
#include <cuda_bf16.h>

// Problem constants (from reference_code)
#define Bn   2
#define NH   8
#define KW   5
#define KK   25       // 5x5 neighbor offsets
#define HD   16       // head_dim = 128/8
#define HC   48       // coarse H
#define WC   48       // coarse W
#define OH   96       // query_height
#define OW   96       // query_width
// scale_factor = 2, dilation = 1, radius = 2

// Output layout: concat(k_nb, v_nb, mask); every plane is 96*96 = 9216 floats.
//   k_nb planes:  [0, 6400)        plane p = ((b*NH + h)*KK + kk)*HD + d
//   v_nb planes:  [6400, 12800)
//   mask planes:  [12800, 13200)   plane p = (b*NH + h)*KK + kk
constexpr int PLANE_KV        = Bn * NH * KK * HD;              // 6400
constexpr int PLANE_MASK_BASE = 2 * PLANE_KV;                   // 12800
constexpr int PLANES          = PLANE_MASK_BASE + Bn * NH * KK; // 13200

constexpr int Q4_PER_ROW = OW / 4;                 // 24 float4 per fine row
constexpr int RHALF      = HC / 2;                 // 24: thread covers cr, cr+24
constexpr int ITEMS      = RHALF * Q4_PER_ROW;     // 576 items per plane
constexpr int TPB        = 288;                    // 2 blocks per plane
constexpr int BLKX       = ITEMS / TPB;            // 2

__device__ __forceinline__ void stcs4(float4* p, float4 v) {
    asm volatile("st.global.cs.v4.f32 [%0], {%1, %2, %3, %4};"
                 :: "l"(p), "f"(v.x), "f"(v.y), "f"(v.z), "f"(v.w) : "memory");
}

__global__ void __launch_bounds__(TPB)
xsn_extract_kernel(const float* __restrict__ kin,
                   const float* __restrict__ vin,
                   float* __restrict__ out)
{
    // ---- block-uniform plane decode ----
    const int plane = blockIdx.y;

    const float* src = kin;
    int p = plane;
    bool is_mask = false;
    if (plane >= PLANE_MASK_BASE) {
        is_mask = true;
        p = plane - PLANE_MASK_BASE;
    } else if (plane >= PLANE_KV) {
        src = vin;
        p = plane - PLANE_KV;
    }

    int kk, base = 0;
    if (is_mask) {
        kk = p % KK;                           // p = bh*25 + kk
    } else {
        int d    = p & (HD - 1);               // p = (bh*25 + kk)*16 + d
        int rest = p >> 4;
        kk       = rest % KK;
        int bh   = rest / KK;                  // b*NH + h
        base     = (bh * HD + d) * (HC * WC);  // channel = bh*16 + d
    }
    const int dy = kk / KW - 2;
    const int dx = kk - (kk / KW) * KW - 2;

    // ---- per-thread: one float4-column qx, two coarse rows (cr, cr+24) ----
    const int item = blockIdx.x * TPB + threadIdx.x;   // 0..575
    const int cr   = item / Q4_PER_ROW;                // coarse row 0..23
    const int qx   = item - cr * Q4_PER_ROW;           // float4 col 0..23

    const int xc0 = (qx << 1) + dx;                    // two coarse source cols
    const int xc1 = xc0 + 1;

    const int ycA = cr + dy;
    const int ycB = cr + RHALF + dy;
    const bool vyA = (unsigned)ycA < (unsigned)HC;
    const bool vyB = (unsigned)ycB < (unsigned)HC;

    float a0, a1, b0, b1;
    if (is_mask) {
        const bool bx0 = (unsigned)xc0 < (unsigned)WC;
        const bool bx1 = (unsigned)xc1 < (unsigned)WC;
        a0 = (vyA && bx0) ? 1.0f : 0.0f;
        a1 = (vyA && bx1) ? 1.0f : 0.0f;
        b0 = (vyB && bx0) ? 1.0f : 0.0f;
        b1 = (vyB && bx1) ? 1.0f : 0.0f;
    } else if ((dx & 1) == 0) {
        // even dx: xc0 even -> aligned float2; pair is all-in or all-out
        // (a partial pair would require odd xc0 or xc1==WC with odd xc0)
        const bool pin = (unsigned)xc0 <= (unsigned)(WC - 2);
        const float2 z2 = make_float2(0.0f, 0.0f);
        const float2 pA = (vyA && pin)
            ? __ldg(reinterpret_cast<const float2*>(src + base + ycA * WC + xc0)) : z2;
        const float2 pB = (vyB && pin)
            ? __ldg(reinterpret_cast<const float2*>(src + base + ycB * WC + xc0)) : z2;
        a0 = pA.x; a1 = pA.y;
        b0 = pB.x; b1 = pB.y;
    } else {
        // odd dx: scalar fallback
        const bool bx0 = (unsigned)xc0 < (unsigned)WC;
        const bool bx1 = (unsigned)xc1 < (unsigned)WC;
        const float* rowA = src + base + ycA * WC;
        const float* rowB = src + base + ycB * WC;
        a0 = (vyA && bx0) ? __ldg(rowA + xc0) : 0.0f;
        a1 = (vyA && bx1) ? __ldg(rowA + xc1) : 0.0f;
        b0 = (vyB && bx0) ? __ldg(rowB + xc0) : 0.0f;
        b1 = (vyB && bx1) ? __ldg(rowB + xc1) : 0.0f;
    }

    const float4 oA = make_float4(a0, a0, a1, a1);
    const float4 oB = make_float4(b0, b0, b1, b1);

    // fine rows 2*cr, 2*cr+1 (copy A); 2*(cr+24), 2*(cr+24)+1 (copy B)
    float4* dst = reinterpret_cast<float4*>(out)
                + plane * (OH * Q4_PER_ROW)            // plane * 2304
                + cr * (2 * Q4_PER_ROW)
                + qx;
    stcs4(dst,                                oA);
    stcs4(dst + Q4_PER_ROW,                   oA);
    stcs4(dst + 2 * RHALF * Q4_PER_ROW,       oB);     // +1152
    stcs4(dst + (2 * RHALF + 1) * Q4_PER_ROW, oB);     // +1176
}

extern "C" void kernel_launch(void* const* d_in, const int* in_sizes, int n_in,
                              void* d_out, int out_size)
{
    const float* k = (const float*)d_in[0];
    const float* v = (const float*)d_in[1];
    float* out = (float*)d_out;

    dim3 grid(BLKX, PLANES, 1);   // (2, 13200)
    xsn_extract_kernel<<<grid, TPB>>>(k, v, out);
}

// round 9
// speedup vs baseline: 1.6878x; 1.0042x over previous
#include <cuda_runtime.h>
#include <cuda_bf16.h>

// Problem constants (from reference_code)
#define Bn   2
#define NH   8
#define KW   5
#define KK   25       // 5x5 neighbor offsets
#define HD   16       // head_dim = 128/8
#define HC   48       // coarse H
#define WC   48       // coarse W
#define OH   96       // query_height
#define OW   96       // query_width
// scale_factor = 2, dilation = 1, radius = 2

// Output layout: concat(k_nb, v_nb, mask); every plane is 96*96 = 9216 floats.
//   k_nb planes:  [0, 6400)        plane p = ((b*NH + h)*KK + kk)*HD + d
//   v_nb planes:  [6400, 12800)
//   mask planes:  [12800, 13200)   plane p = (b*NH + h)*KK + kk
constexpr int PLANE_KV        = Bn * NH * KK * HD;              // 6400
constexpr int PLANE_MASK_BASE = 2 * PLANE_KV;                   // 12800
constexpr int PLANES          = PLANE_MASK_BASE + Bn * NH * KK; // 13200

constexpr int Q4_PER_ROW = OW / 4;     // 24 float4 per fine row
constexpr int RSTRIDE    = 12;         // thread covers cr, cr+12, cr+24, cr+36

__device__ __forceinline__ void stcs4(float4* p, float4 v) {
    asm volatile("st.global.cs.v4.f32 [%0], {%1, %2, %3, %4};"
                 :: "l"(p), "f"(v.x), "f"(v.y), "f"(v.z), "f"(v.w) : "memory");
}

__global__ void __launch_bounds__(288)
xsn_extract_kernel(const float* __restrict__ kin,
                   const float* __restrict__ vin,
                   float* __restrict__ out)
{
    // ---- block-uniform plane decode (one block == one output plane) ----
    const int plane = blockIdx.x;

    const float* src = kin;
    int p = plane;
    bool is_mask = false;
    if (plane >= PLANE_MASK_BASE) {
        is_mask = true;
        p = plane - PLANE_MASK_BASE;
    } else if (plane >= PLANE_KV) {
        src = vin;
        p = plane - PLANE_KV;
    }

    int kk, base = 0;
    if (is_mask) {
        kk = p % KK;                           // p = bh*25 + kk
    } else {
        int d    = p & (HD - 1);               // p = (bh*25 + kk)*16 + d
        int rest = p >> 4;
        kk       = rest % KK;
        int bh   = rest / KK;                  // b*NH + h
        base     = (bh * HD + d) * (HC * WC);  // channel = bh*16 + d
    }
    const int dy = kk / KW - 2;
    const int dx = kk - (kk / KW) * KW - 2;

    // ---- per-thread: qx = threadIdx.x (0..23), base coarse row = threadIdx.y (0..11)
    const int qx = threadIdx.x;
    const int cr = threadIdx.y;

    const int xc0 = (qx << 1) + dx;
    const int xc1 = xc0 + 1;

    float4 o[4];

    if (is_mask) {
        const bool bx0 = (unsigned)xc0 < (unsigned)WC;
        const bool bx1 = (unsigned)xc1 < (unsigned)WC;
        #pragma unroll
        for (int i = 0; i < 4; i++) {
            const int yc = cr + i * RSTRIDE + dy;
            const bool vy = (unsigned)yc < (unsigned)HC;
            o[i] = make_float4(vy && bx0 ? 1.0f : 0.0f, vy && bx0 ? 1.0f : 0.0f,
                               vy && bx1 ? 1.0f : 0.0f, vy && bx1 ? 1.0f : 0.0f);
        }
    } else if ((dx & 1) == 0) {
        // even dx: xc0 even -> aligned float2; the pair is all-in or all-out
        const bool pin = (unsigned)xc0 <= (unsigned)(WC - 2);
        #pragma unroll
        for (int i = 0; i < 4; i++) {
            const int yc = cr + i * RSTRIDE + dy;
            const bool vy = (unsigned)yc < (unsigned)HC;
            float2 pr = (vy && pin)
                ? __ldg(reinterpret_cast<const float2*>(src + base + yc * WC + xc0))
                : make_float2(0.0f, 0.0f);
            o[i] = make_float4(pr.x, pr.x, pr.y, pr.y);
        }
    } else {
        // odd dx: scalar fallback
        const bool bx0 = (unsigned)xc0 < (unsigned)WC;
        const bool bx1 = (unsigned)xc1 < (unsigned)WC;
        #pragma unroll
        for (int i = 0; i < 4; i++) {
            const int yc = cr + i * RSTRIDE + dy;
            const bool vy = (unsigned)yc < (unsigned)HC;
            const float* rowp = src + base + yc * WC;
            float v0 = (vy && bx0) ? __ldg(rowp + xc0) : 0.0f;
            float v1 = (vy && bx1) ? __ldg(rowp + xc1) : 0.0f;
            o[i] = make_float4(v0, v0, v1, v1);
        }
    }

    // fine rows 2*(cr + i*12) and 2*(cr + i*12)+1 get copy o[i]
    float4* dst = reinterpret_cast<float4*>(out)
                + plane * (OH * Q4_PER_ROW)            // plane * 2304
                + cr * (2 * Q4_PER_ROW)
                + qx;
    #pragma unroll
    for (int i = 0; i < 4; i++) {
        float4* d2 = dst + i * (2 * RSTRIDE * Q4_PER_ROW);  // +i*576
        stcs4(d2,              o[i]);
        stcs4(d2 + Q4_PER_ROW, o[i]);
    }
}

extern "C" void kernel_launch(void* const* d_in, const int* in_sizes, int n_in,
                              void* d_out, int out_size)
{
    const float* k = (const float*)d_in[0];
    const float* v = (const float*)d_in[1];
    float* out = (float*)d_out;

    dim3 block(Q4_PER_ROW, RSTRIDE, 1);   // (24, 12) = 288 threads
    xsn_extract_kernel<<<PLANES, block>>>(k, v, out);
}